// round 1
// baseline (speedup 1.0000x reference)
#include <cuda_runtime.h>
#include <math.h>

#define TOKENS  8192
#define D_MODEL 2048
#define D_FF    8192

// ---------------- scratch (static device globals; no allocation) ----------------
__device__ double      g_part[2][1024];
__device__ float       g_wscale[2];
__device__ signed char g_w1q[(size_t)D_FF * D_MODEL];   // 16 MB
__device__ signed char g_w2q[(size_t)D_MODEL * D_FF];   // 16 MB
__device__ signed char g_xq [(size_t)TOKENS * D_MODEL]; // 16 MB
__device__ float       g_xinv[TOKENS];
__device__ float       g_h  [(size_t)TOKENS * D_FF];    // 256 MB
__device__ signed char g_hq [(size_t)TOKENS * D_FF];    // 64 MB
__device__ float       g_hinv[TOKENS];

// ---------------- weight absmean (deterministic two-stage reduction) ----------------
__global__ void absmean_stage1(const float* __restrict__ w, size_t n, int idx) {
    __shared__ double sh[256];
    double s = 0.0;
    for (size_t i = (size_t)blockIdx.x * 256 + threadIdx.x; i < n; i += (size_t)256 * 1024)
        s += fabsf(w[i]);
    sh[threadIdx.x] = s; __syncthreads();
    for (int st = 128; st > 0; st >>= 1) {
        if (threadIdx.x < st) sh[threadIdx.x] += sh[threadIdx.x + st];
        __syncthreads();
    }
    if (threadIdx.x == 0) g_part[idx][blockIdx.x] = sh[0];
}

__global__ void absmean_stage2(size_t n, int idx) {
    __shared__ double sh[256];
    int tid = threadIdx.x;
    double s = g_part[idx][tid] + g_part[idx][tid + 256] +
               g_part[idx][tid + 512] + g_part[idx][tid + 768];
    sh[tid] = s; __syncthreads();
    for (int st = 128; st > 0; st >>= 1) {
        if (tid < st) sh[tid] += sh[tid + st];
        __syncthreads();
    }
    if (tid == 0) {
        double m = sh[0] / (double)n;
        g_wscale[idx] = (float)fmax(m, 1e-8);
    }
}

// ---------------- ternary weight quantization ----------------
__global__ void quant_w_kernel(const float* __restrict__ w, size_t n, int idx) {
    float s = g_wscale[idx];
    signed char* q = (idx == 0) ? g_w1q : g_w2q;
    for (size_t i = (size_t)blockIdx.x * blockDim.x + threadIdx.x; i < n;
         i += (size_t)gridDim.x * blockDim.x) {
        float v = rintf(w[i] / s);           // round-half-even like jnp.round
        v = fmaxf(-1.0f, fminf(1.0f, v));
        q[i] = (signed char)v;
    }
}

// ---------------- fused LN + per-token absmax int8 quant (x: d=2048) ----------------
__global__ void ln_quant_x_kernel(const float* __restrict__ x) {
    __shared__ float sh[256];
    const int t = blockIdx.x, tid = threadIdx.x;
    const float4* rp = (const float4*)(x + (size_t)t * D_MODEL);
    float4 v0 = rp[tid], v1 = rp[tid + 256];

    float s = v0.x + v0.y + v0.z + v0.w + v1.x + v1.y + v1.z + v1.w;
    sh[tid] = s; __syncthreads();
    for (int st = 128; st > 0; st >>= 1) { if (tid < st) sh[tid] += sh[tid + st]; __syncthreads(); }
    float mu = sh[0] * (1.0f / D_MODEL); __syncthreads();

    v0.x -= mu; v0.y -= mu; v0.z -= mu; v0.w -= mu;
    v1.x -= mu; v1.y -= mu; v1.z -= mu; v1.w -= mu;
    float vs = v0.x*v0.x + v0.y*v0.y + v0.z*v0.z + v0.w*v0.w
             + v1.x*v1.x + v1.y*v1.y + v1.z*v1.z + v1.w*v1.w;
    sh[tid] = vs; __syncthreads();
    for (int st = 128; st > 0; st >>= 1) { if (tid < st) sh[tid] += sh[tid + st]; __syncthreads(); }
    float var = sh[0] * (1.0f / D_MODEL); __syncthreads();
    float rstd = 1.0f / sqrtf(var + 1e-5f);

    v0.x *= rstd; v0.y *= rstd; v0.z *= rstd; v0.w *= rstd;
    v1.x *= rstd; v1.y *= rstd; v1.z *= rstd; v1.w *= rstd;
    float am = fmaxf(fmaxf(fmaxf(fabsf(v0.x), fabsf(v0.y)), fmaxf(fabsf(v0.z), fabsf(v0.w))),
                     fmaxf(fmaxf(fabsf(v1.x), fabsf(v1.y)), fmaxf(fabsf(v1.z), fabsf(v1.w))));
    sh[tid] = am; __syncthreads();
    for (int st = 128; st > 0; st >>= 1) { if (tid < st) sh[tid] = fmaxf(sh[tid], sh[tid + st]); __syncthreads(); }
    float amax = fmaxf(sh[0], 1e-5f); __syncthreads();
    float scale = 127.0f / amax;

    char4 c0, c1;
    c0.x = (signed char)fminf(127.f, fmaxf(-128.f, rintf(v0.x * scale)));
    c0.y = (signed char)fminf(127.f, fmaxf(-128.f, rintf(v0.y * scale)));
    c0.z = (signed char)fminf(127.f, fmaxf(-128.f, rintf(v0.z * scale)));
    c0.w = (signed char)fminf(127.f, fmaxf(-128.f, rintf(v0.w * scale)));
    c1.x = (signed char)fminf(127.f, fmaxf(-128.f, rintf(v1.x * scale)));
    c1.y = (signed char)fminf(127.f, fmaxf(-128.f, rintf(v1.y * scale)));
    c1.z = (signed char)fminf(127.f, fmaxf(-128.f, rintf(v1.z * scale)));
    c1.w = (signed char)fminf(127.f, fmaxf(-128.f, rintf(v1.w * scale)));
    char4* qp = (char4*)(g_xq + (size_t)t * D_MODEL);
    qp[tid] = c0; qp[tid + 256] = c1;
    if (tid == 0) g_xinv[t] = amax * (1.0f / 127.0f);
}

// ---------------- fused LN + quant (h: d=8192) ----------------
__global__ void ln_quant_h_kernel() {
    __shared__ float sh[256];
    const int t = blockIdx.x, tid = threadIdx.x;
    const float4* rp = (const float4*)(g_h + (size_t)t * D_FF);
    float4 v[8];
    float s = 0.f;
#pragma unroll
    for (int j = 0; j < 8; j++) { v[j] = rp[j * 256 + tid]; s += v[j].x + v[j].y + v[j].z + v[j].w; }
    sh[tid] = s; __syncthreads();
    for (int st = 128; st > 0; st >>= 1) { if (tid < st) sh[tid] += sh[tid + st]; __syncthreads(); }
    float mu = sh[0] * (1.0f / D_FF); __syncthreads();

    float vs = 0.f;
#pragma unroll
    for (int j = 0; j < 8; j++) {
        v[j].x -= mu; v[j].y -= mu; v[j].z -= mu; v[j].w -= mu;
        vs += v[j].x*v[j].x + v[j].y*v[j].y + v[j].z*v[j].z + v[j].w*v[j].w;
    }
    sh[tid] = vs; __syncthreads();
    for (int st = 128; st > 0; st >>= 1) { if (tid < st) sh[tid] += sh[tid + st]; __syncthreads(); }
    float var = sh[0] * (1.0f / D_FF); __syncthreads();
    float rstd = 1.0f / sqrtf(var + 1e-5f);

    float am = 0.f;
#pragma unroll
    for (int j = 0; j < 8; j++) {
        v[j].x *= rstd; v[j].y *= rstd; v[j].z *= rstd; v[j].w *= rstd;
        am = fmaxf(am, fmaxf(fmaxf(fabsf(v[j].x), fabsf(v[j].y)), fmaxf(fabsf(v[j].z), fabsf(v[j].w))));
    }
    sh[tid] = am; __syncthreads();
    for (int st = 128; st > 0; st >>= 1) { if (tid < st) sh[tid] = fmaxf(sh[tid], sh[tid + st]); __syncthreads(); }
    float amax = fmaxf(sh[0], 1e-5f); __syncthreads();
    float scale = 127.0f / amax;

    char4* qp = (char4*)(g_hq + (size_t)t * D_FF);
#pragma unroll
    for (int j = 0; j < 8; j++) {
        char4 c;
        c.x = (signed char)fminf(127.f, fmaxf(-128.f, rintf(v[j].x * scale)));
        c.y = (signed char)fminf(127.f, fmaxf(-128.f, rintf(v[j].y * scale)));
        c.z = (signed char)fminf(127.f, fmaxf(-128.f, rintf(v[j].z * scale)));
        c.w = (signed char)fminf(127.f, fmaxf(-128.f, rintf(v[j].w * scale)));
        qp[j * 256 + tid] = c;
    }
    if (tid == 0) g_hinv[t] = amax * (1.0f / 127.0f);
}

// ---------------- int8 dp4a GEMM mainloop: 64x64 tile, BK=64, 256 thr, 4x4/thread ----------------
// smem row stride 80B (16B aligned). Thread (tr=tid>>4, tc=tid&15) owns rows m0+4tr+i,
// cols n0+tc+16j (B fragment at consecutive rows tc -> conflict-free LDS.128).
__device__ __forceinline__ void gemm_mainloop(
    const signed char* __restrict__ Ag, const signed char* __restrict__ Bg,
    int lda, int ldb, int kIters,
    signed char* As, signed char* Bs, int acc[4][4])
{
    const int tid   = threadIdx.x;
    const int lrow  = tid >> 2, lchunk = tid & 3;
    const int tr    = tid >> 4, tc = tid & 15;

    for (int kt = 0; kt < kIters; ++kt) {
        const int k0 = kt * 64;
        *(int4*)(As + lrow * 80 + lchunk * 16) =
            *(const int4*)(Ag + (size_t)lrow * lda + k0 + lchunk * 16);
        *(int4*)(Bs + lrow * 80 + lchunk * 16) =
            *(const int4*)(Bg + (size_t)lrow * ldb + k0 + lchunk * 16);
        __syncthreads();
#pragma unroll
        for (int kk = 0; kk < 4; kk++) {
            int4 a[4], b[4];
#pragma unroll
            for (int i = 0; i < 4; i++) a[i] = *(const int4*)(As + (4 * tr + i) * 80 + kk * 16);
#pragma unroll
            for (int j = 0; j < 4; j++) b[j] = *(const int4*)(Bs + (tc + 16 * j) * 80 + kk * 16);
#pragma unroll
            for (int i = 0; i < 4; i++)
#pragma unroll
                for (int j = 0; j < 4; j++) {
                    int s = acc[i][j];
                    s = __dp4a(a[i].x, b[j].x, s);
                    s = __dp4a(a[i].y, b[j].y, s);
                    s = __dp4a(a[i].z, b[j].z, s);
                    s = __dp4a(a[i].w, b[j].w, s);
                    acc[i][j] = s;
                }
        }
        __syncthreads();
    }
}

__device__ __forceinline__ float gelu_exact(float x) {
    return 0.5f * x * (1.0f + erff(x * 0.7071067811865476f));
}

// ---------------- GEMM1: h = gelu(xq @ w1q^T * scales + b1) ----------------
__global__ void __launch_bounds__(256) gemm1_kernel(const float* __restrict__ b1) {
    __shared__ signed char As[64 * 80];
    __shared__ signed char Bs[64 * 80];
    const int m0 = blockIdx.y * 64, n0 = blockIdx.x * 64;
    int acc[4][4];
#pragma unroll
    for (int i = 0; i < 4; i++)
#pragma unroll
        for (int j = 0; j < 4; j++) acc[i][j] = 0;

    gemm_mainloop(g_xq + (size_t)m0 * D_MODEL, g_w1q + (size_t)n0 * D_MODEL,
                  D_MODEL, D_MODEL, D_MODEL / 64, As, Bs, acc);

    const float ws = g_wscale[0];
    const int tr = threadIdx.x >> 4, tc = threadIdx.x & 15;
#pragma unroll
    for (int i = 0; i < 4; i++) {
        const int t = m0 + 4 * tr + i;
        const float xs = g_xinv[t] * ws;
        float* hrow = g_h + (size_t)t * D_FF;
#pragma unroll
        for (int j = 0; j < 4; j++) {
            const int f = n0 + tc + 16 * j;
            float val = (float)acc[i][j] * xs + b1[f];
            hrow[f] = gelu_exact(val);
        }
    }
}

// ---------------- GEMM2: out = hq @ w2q^T * scales + b2 ----------------
__global__ void __launch_bounds__(256) gemm2_kernel(const float* __restrict__ b2,
                                                    float* __restrict__ out) {
    __shared__ signed char As[64 * 80];
    __shared__ signed char Bs[64 * 80];
    const int m0 = blockIdx.y * 64, n0 = blockIdx.x * 64;
    int acc[4][4];
#pragma unroll
    for (int i = 0; i < 4; i++)
#pragma unroll
        for (int j = 0; j < 4; j++) acc[i][j] = 0;

    gemm_mainloop(g_hq + (size_t)m0 * D_FF, g_w2q + (size_t)n0 * D_FF,
                  D_FF, D_FF, D_FF / 64, As, Bs, acc);

    const float ws = g_wscale[1];
    const int tr = threadIdx.x >> 4, tc = threadIdx.x & 15;
#pragma unroll
    for (int i = 0; i < 4; i++) {
        const int t = m0 + 4 * tr + i;
        const float hs = g_hinv[t] * ws;
        float* orow = out + (size_t)t * D_MODEL;
#pragma unroll
        for (int j = 0; j < 4; j++) {
            const int f = n0 + tc + 16 * j;
            orow[f] = (float)acc[i][j] * hs + b2[f];
        }
    }
}

// ---------------- launch ----------------
extern "C" void kernel_launch(void* const* d_in, const int* in_sizes, int n_in,
                              void* d_out, int out_size) {
    (void)in_sizes; (void)n_in; (void)out_size;
    const float* x  = (const float*)d_in[0];
    const float* w1 = (const float*)d_in[1];
    const float* b1 = (const float*)d_in[2];
    const float* w2 = (const float*)d_in[3];
    const float* b2 = (const float*)d_in[4];
    float* out = (float*)d_out;

    const size_t NW = (size_t)D_FF * D_MODEL;

    absmean_stage1<<<1024, 256>>>(w1, NW, 0);
    absmean_stage1<<<1024, 256>>>(w2, NW, 1);
    absmean_stage2<<<1, 256>>>(NW, 0);
    absmean_stage2<<<1, 256>>>(NW, 1);
    quant_w_kernel<<<4096, 256>>>(w1, NW, 0);
    quant_w_kernel<<<4096, 256>>>(w2, NW, 1);
    ln_quant_x_kernel<<<TOKENS, 256>>>(x);
    gemm1_kernel<<<dim3(D_FF / 64, TOKENS / 64), 256>>>(b1);
    ln_quant_h_kernel<<<TOKENS, 256>>>();
    gemm2_kernel<<<dim3(D_MODEL / 64, TOKENS / 64), 256>>>(b2, out);
}

// round 4
// speedup vs baseline: 1.0871x; 1.0871x over previous
#include <cuda_runtime.h>
#include <math.h>
#include <stdint.h>

#define TOKENS  8192
#define D_MODEL 2048
#define D_FF    8192

// ---------------- scratch (static device globals; no allocation) ----------------
__device__ double      g_part[2][1024];
__device__ float       g_wscale[2];
__device__ signed char g_w1q[(size_t)D_FF * D_MODEL];
__device__ signed char g_w2q[(size_t)D_MODEL * D_FF];
__device__ signed char g_xq [(size_t)TOKENS * D_MODEL];
__device__ float       g_xinv[TOKENS];
__device__ float       g_h  [(size_t)TOKENS * D_FF];
__device__ signed char g_hq [(size_t)TOKENS * D_FF];
__device__ float       g_hinv[TOKENS];

// ---------------- PTX helpers ----------------
__device__ __forceinline__ uint32_t s2u(const void* p) {
    uint32_t a;
    asm("{ .reg .u64 t; cvta.to.shared.u64 t, %1; cvt.u32.u64 %0, t; }" : "=r"(a) : "l"(p));
    return a;
}
#define CP_ASYNC16(s, g) \
    asm volatile("cp.async.cg.shared.global [%0], [%1], 16;" :: "r"(s), "l"(g) : "memory")
#define CP_COMMIT()  asm volatile("cp.async.commit_group;" ::: "memory")
#define CP_WAIT(n)   asm volatile("cp.async.wait_group %0;" :: "n"(n) : "memory")

#define LDSM_X4(r, a) \
    asm volatile("ldmatrix.sync.aligned.m8n8.x4.shared.b16 {%0,%1,%2,%3}, [%4];" \
        : "=r"((r)[0]), "=r"((r)[1]), "=r"((r)[2]), "=r"((r)[3]) : "r"(a))

#define MMA_S8(d, a, b0v, b1v) \
    asm volatile("mma.sync.aligned.m16n8k32.row.col.s32.s8.s8.s32 " \
        "{%0,%1,%2,%3}, {%4,%5,%6,%7}, {%8,%9}, {%0,%1,%2,%3};" \
        : "+r"((d)[0]), "+r"((d)[1]), "+r"((d)[2]), "+r"((d)[3]) \
        : "r"((a)[0]), "r"((a)[1]), "r"((a)[2]), "r"((a)[3]), "r"(b0v), "r"(b1v))

// ---------------- stage a 128-row x 64B tile into smem (stride 80, conflict-free) ----------------
__device__ __forceinline__ void stage128(const signed char* g, int ld, uint32_t sbase, int tid) {
#pragma unroll
    for (int it = 0; it < 2; ++it) {
        int l = tid + it * 256;           // 512 chunks total
        int row = l >> 2, c = l & 3;
        CP_ASYNC16(sbase + row * 80 + c * 16,
                   g + (size_t)row * ld + c * 16);
    }
}

// ---------------- int8 tensor-core GEMM: out[M,N] = A[M,K] * B[N,K]^T ----------------
// block 128x128, BK=64, 8 warps (warpM 0..1 x warpN 0..3), warp tile 64x32
template <int MODE>  // 1: xq@w1 +bias+gelu -> g_h ; 2: hq@w2 +bias -> out
__global__ void __launch_bounds__(256) gemm_imma(const float* __restrict__ bias,
                                                 float* __restrict__ outp) {
    __shared__ signed char sA[2][128 * 80];
    __shared__ signed char sB[2][128 * 80];

    constexpr int K = (MODE == 1) ? D_MODEL : D_FF;
    constexpr int KITERS = K / 64;
    constexpr int LDOUT = (MODE == 1) ? D_FF : D_MODEL;
    const signed char* A = (MODE == 1) ? g_xq : g_hq;
    const signed char* B = (MODE == 1) ? g_w1q : g_w2q;
    const float* rowinv = (MODE == 1) ? g_xinv : g_hinv;
    float* out = (MODE == 1) ? g_h : outp;

    const int tid = threadIdx.x;
    const int wid = tid >> 5, lane = tid & 31;
    const int warpM = wid >> 2, warpN = wid & 3;
    const int m0 = blockIdx.y * 128, n0 = blockIdx.x * 128;

    const signed char* Abase = A + (size_t)m0 * K;
    const signed char* Bbase = B + (size_t)n0 * K;

    const uint32_t sa[2] = {s2u(sA[0]), s2u(sA[1])};
    const uint32_t sb[2] = {s2u(sB[0]), s2u(sB[1])};

    // ldmatrix per-lane address offsets (row stride 80)
    const int lr = lane & 7, g = lane >> 3;
    const uint32_t a_off = (uint32_t)((lr + (g & 1) * 8) * 80 + (g >> 1) * 16);
    const uint32_t b_off = (uint32_t)((lr + (g >> 1) * 8) * 80 + (g & 1) * 16);

    int acc[4][4][4];
#pragma unroll
    for (int i = 0; i < 4; i++)
#pragma unroll
        for (int j = 0; j < 4; j++)
#pragma unroll
            for (int r = 0; r < 4; r++) acc[i][j][r] = 0;

    // prologue
    stage128(Abase, K, sa[0], tid);
    stage128(Bbase, K, sb[0], tid);
    CP_COMMIT();

    for (int kt = 0; kt < KITERS; ++kt) {
        const int cur = kt & 1;
        if (kt + 1 < KITERS) {
            stage128(Abase + (kt + 1) * 64, K, sa[cur ^ 1], tid);
            stage128(Bbase + (kt + 1) * 64, K, sb[cur ^ 1], tid);
            CP_COMMIT();
            CP_WAIT(1);
        } else {
            CP_WAIT(0);
        }
        __syncthreads();

        const uint32_t Ab = sa[cur] + (uint32_t)(warpM * 64 * 80) + a_off;
        const uint32_t Bb = sb[cur] + (uint32_t)(warpN * 32 * 80) + b_off;
#pragma unroll
        for (int ks = 0; ks < 2; ++ks) {
            uint32_t ar[4][4], br[2][4];
#pragma unroll
            for (int i = 0; i < 4; i++) LDSM_X4(ar[i], Ab + i * 1280 + ks * 32);
#pragma unroll
            for (int jp = 0; jp < 2; jp++) LDSM_X4(br[jp], Bb + jp * 1280 + ks * 32);
#pragma unroll
            for (int i = 0; i < 4; i++)
#pragma unroll
                for (int j = 0; j < 4; j++)
                    MMA_S8(acc[i][j], ar[i], br[j >> 1][(j & 1) * 2], br[j >> 1][(j & 1) * 2 + 1]);
        }
        __syncthreads();
    }

    // ---------------- epilogue: scale + bias (+gelu), direct float2 stores ----------------
    const float ws = g_wscale[MODE - 1];
    const int rbase = m0 + warpM * 64 + (lane >> 2);
    const int cbase = n0 + warpN * 32 + (lane & 3) * 2;
#pragma unroll
    for (int i = 0; i < 4; i++) {
        const int r0 = rbase + i * 16;
        const float sc0 = rowinv[r0] * ws;
        const float sc1 = rowinv[r0 + 8] * ws;
#pragma unroll
        for (int j = 0; j < 4; j++) {
            const int c = cbase + j * 8;
            const float bx = bias[c], by = bias[c + 1];
            float2 v0, v1;
            v0.x = (float)acc[i][j][0] * sc0 + bx;
            v0.y = (float)acc[i][j][1] * sc0 + by;
            v1.x = (float)acc[i][j][2] * sc1 + bx;
            v1.y = (float)acc[i][j][3] * sc1 + by;
            if (MODE == 1) {
                v0.x = 0.5f * v0.x * (1.0f + erff(v0.x * 0.7071067811865476f));
                v0.y = 0.5f * v0.y * (1.0f + erff(v0.y * 0.7071067811865476f));
                v1.x = 0.5f * v1.x * (1.0f + erff(v1.x * 0.7071067811865476f));
                v1.y = 0.5f * v1.y * (1.0f + erff(v1.y * 0.7071067811865476f));
            }
            *(float2*)(out + (size_t)r0 * LDOUT + c) = v0;
            *(float2*)(out + (size_t)(r0 + 8) * LDOUT + c) = v1;
        }
    }
}

// ---------------- weight absmean (deterministic two-stage) ----------------
__global__ void absmean_stage1(const float* __restrict__ w, size_t n, int idx) {
    __shared__ double sh[256];
    double s = 0.0;
    for (size_t i = (size_t)blockIdx.x * 256 + threadIdx.x; i < n; i += (size_t)256 * 1024)
        s += fabsf(w[i]);
    sh[threadIdx.x] = s; __syncthreads();
    for (int st = 128; st > 0; st >>= 1) {
        if (threadIdx.x < st) sh[threadIdx.x] += sh[threadIdx.x + st];
        __syncthreads();
    }
    if (threadIdx.x == 0) g_part[idx][blockIdx.x] = sh[0];
}

__global__ void absmean_stage2(size_t n, int idx) {
    __shared__ double sh[256];
    int tid = threadIdx.x;
    double s = g_part[idx][tid] + g_part[idx][tid + 256] +
               g_part[idx][tid + 512] + g_part[idx][tid + 768];
    sh[tid] = s; __syncthreads();
    for (int st = 128; st > 0; st >>= 1) {
        if (tid < st) sh[tid] += sh[tid + st];
        __syncthreads();
    }
    if (tid == 0) g_wscale[idx] = (float)fmax(sh[0] / (double)n, 1e-8);
}

// ---------------- ternary weight quant ----------------
__global__ void quant_w_kernel(const float* __restrict__ w, size_t n, int idx) {
    float s = g_wscale[idx];
    signed char* q = (idx == 0) ? g_w1q : g_w2q;
    for (size_t i = (size_t)blockIdx.x * blockDim.x + threadIdx.x; i < n;
         i += (size_t)gridDim.x * blockDim.x) {
        float v = rintf(w[i] / s);
        v = fmaxf(-1.0f, fminf(1.0f, v));
        q[i] = (signed char)v;
    }
}

// ---------------- fused LN + per-token absmax int8 quant (x: d=2048) ----------------
__global__ void ln_quant_x_kernel(const float* __restrict__ x) {
    __shared__ float sh[256];
    const int t = blockIdx.x, tid = threadIdx.x;
    const float4* rp = (const float4*)(x + (size_t)t * D_MODEL);
    float4 v0 = rp[tid], v1 = rp[tid + 256];

    float s = v0.x + v0.y + v0.z + v0.w + v1.x + v1.y + v1.z + v1.w;
    sh[tid] = s; __syncthreads();
    for (int st = 128; st > 0; st >>= 1) { if (tid < st) sh[tid] += sh[tid + st]; __syncthreads(); }
    float mu = sh[0] * (1.0f / D_MODEL); __syncthreads();

    v0.x -= mu; v0.y -= mu; v0.z -= mu; v0.w -= mu;
    v1.x -= mu; v1.y -= mu; v1.z -= mu; v1.w -= mu;
    float vs = v0.x*v0.x + v0.y*v0.y + v0.z*v0.z + v0.w*v0.w
             + v1.x*v1.x + v1.y*v1.y + v1.z*v1.z + v1.w*v1.w;
    sh[tid] = vs; __syncthreads();
    for (int st = 128; st > 0; st >>= 1) { if (tid < st) sh[tid] += sh[tid + st]; __syncthreads(); }
    float rstd = rsqrtf(sh[0] * (1.0f / D_MODEL) + 1e-5f); __syncthreads();

    v0.x *= rstd; v0.y *= rstd; v0.z *= rstd; v0.w *= rstd;
    v1.x *= rstd; v1.y *= rstd; v1.z *= rstd; v1.w *= rstd;
    float am = fmaxf(fmaxf(fmaxf(fabsf(v0.x), fabsf(v0.y)), fmaxf(fabsf(v0.z), fabsf(v0.w))),
                     fmaxf(fmaxf(fabsf(v1.x), fabsf(v1.y)), fmaxf(fabsf(v1.z), fabsf(v1.w))));
    sh[tid] = am; __syncthreads();
    for (int st = 128; st > 0; st >>= 1) { if (tid < st) sh[tid] = fmaxf(sh[tid], sh[tid + st]); __syncthreads(); }
    float amax = fmaxf(sh[0], 1e-5f); __syncthreads();
    float scale = 127.0f / amax;

#define QV(a) (signed char)fminf(127.f, fmaxf(-128.f, rintf((a) * scale)))
    char4 c0, c1;
    c0.x = QV(v0.x); c0.y = QV(v0.y); c0.z = QV(v0.z); c0.w = QV(v0.w);
    c1.x = QV(v1.x); c1.y = QV(v1.y); c1.z = QV(v1.z); c1.w = QV(v1.w);
    char4* qp = (char4*)(g_xq + (size_t)t * D_MODEL);
    qp[tid] = c0; qp[tid + 256] = c1;
    if (tid == 0) g_xinv[t] = amax * (1.0f / 127.0f);
}

// ---------------- fused LN + quant (h: d=8192) ----------------
__global__ void ln_quant_h_kernel() {
    __shared__ float sh[256];
    const int t = blockIdx.x, tid = threadIdx.x;
    const float4* rp = (const float4*)(g_h + (size_t)t * D_FF);
    float4 v[8];
    float s = 0.f;
#pragma unroll
    for (int j = 0; j < 8; j++) { v[j] = rp[j * 256 + tid]; s += v[j].x + v[j].y + v[j].z + v[j].w; }
    sh[tid] = s; __syncthreads();
    for (int st = 128; st > 0; st >>= 1) { if (tid < st) sh[tid] += sh[tid + st]; __syncthreads(); }
    float mu = sh[0] * (1.0f / D_FF); __syncthreads();

    float vs = 0.f;
#pragma unroll
    for (int j = 0; j < 8; j++) {
        v[j].x -= mu; v[j].y -= mu; v[j].z -= mu; v[j].w -= mu;
        vs += v[j].x*v[j].x + v[j].y*v[j].y + v[j].z*v[j].z + v[j].w*v[j].w;
    }
    sh[tid] = vs; __syncthreads();
    for (int st = 128; st > 0; st >>= 1) { if (tid < st) sh[tid] += sh[tid + st]; __syncthreads(); }
    float rstd = rsqrtf(sh[0] * (1.0f / D_FF) + 1e-5f); __syncthreads();

    float am = 0.f;
#pragma unroll
    for (int j = 0; j < 8; j++) {
        v[j].x *= rstd; v[j].y *= rstd; v[j].z *= rstd; v[j].w *= rstd;
        am = fmaxf(am, fmaxf(fmaxf(fabsf(v[j].x), fabsf(v[j].y)), fmaxf(fabsf(v[j].z), fabsf(v[j].w))));
    }
    sh[tid] = am; __syncthreads();
    for (int st = 128; st > 0; st >>= 1) { if (tid < st) sh[tid] = fmaxf(sh[tid], sh[tid + st]); __syncthreads(); }
    float amax = fmaxf(sh[0], 1e-5f); __syncthreads();
    float scale = 127.0f / amax;

    char4* qp = (char4*)(g_hq + (size_t)t * D_FF);
#pragma unroll
    for (int j = 0; j < 8; j++) {
        char4 c;
        c.x = QV(v[j].x); c.y = QV(v[j].y); c.z = QV(v[j].z); c.w = QV(v[j].w);
        qp[j * 256 + tid] = c;
    }
    if (tid == 0) g_hinv[t] = amax * (1.0f / 127.0f);
}

// ---------------- launch ----------------
extern "C" void kernel_launch(void* const* d_in, const int* in_sizes, int n_in,
                              void* d_out, int out_size) {
    (void)in_sizes; (void)n_in; (void)out_size;
    const float* x  = (const float*)d_in[0];
    const float* w1 = (const float*)d_in[1];
    const float* b1 = (const float*)d_in[2];
    const float* w2 = (const float*)d_in[3];
    const float* b2 = (const float*)d_in[4];
    float* out = (float*)d_out;

    const size_t NW = (size_t)D_FF * D_MODEL;

    absmean_stage1<<<1024, 256>>>(w1, NW, 0);
    absmean_stage1<<<1024, 256>>>(w2, NW, 1);
    absmean_stage2<<<1, 256>>>(NW, 0);
    absmean_stage2<<<1, 256>>>(NW, 1);
    quant_w_kernel<<<4096, 256>>>(w1, NW, 0);
    quant_w_kernel<<<4096, 256>>>(w2, NW, 1);
    ln_quant_x_kernel<<<TOKENS, 256>>>(x);
    gemm_imma<1><<<dim3(D_FF / 128, TOKENS / 128), 256>>>(b1, nullptr);
    ln_quant_h_kernel<<<TOKENS, 256>>>();
    gemm_imma<2><<<dim3(D_MODEL / 128, TOKENS / 128), 256>>>(b2, out);
}

// round 5
// speedup vs baseline: 2.9235x; 2.6892x over previous
#include <cuda_runtime.h>
#include <cuda_bf16.h>
#include <math.h>
#include <stdint.h>

#define TOKENS  8192
#define D_MODEL 2048
#define D_FF    8192

// ---------------- scratch (static device globals) ----------------
__device__ double        g_part[2][1024];
__device__ float         g_wscale[2];
__device__ __nv_bfloat16 g_w1q[(size_t)D_FF * D_MODEL];
__device__ __nv_bfloat16 g_w2q[(size_t)D_MODEL * D_FF];
__device__ __nv_bfloat16 g_xq [(size_t)TOKENS * D_MODEL];
__device__ float         g_xinv[TOKENS];
__device__ float         g_h  [(size_t)TOKENS * D_FF];
__device__ __nv_bfloat16 g_hq [(size_t)TOKENS * D_FF];
__device__ float         g_hinv[TOKENS];

// ---------------- PTX helpers ----------------
__device__ __forceinline__ uint32_t s2u(const void* p) {
    uint32_t a;
    asm("{ .reg .u64 t; cvta.to.shared.u64 t, %1; cvt.u32.u64 %0, t; }" : "=r"(a) : "l"(p));
    return a;
}
#define CP_ASYNC16(s, g) \
    asm volatile("cp.async.cg.shared.global [%0], [%1], 16;" :: "r"(s), "l"(g) : "memory")
#define CP_COMMIT()  asm volatile("cp.async.commit_group;" ::: "memory")
#define CP_WAIT(n)   asm volatile("cp.async.wait_group %0;" :: "n"(n) : "memory")

#define LDSM_X4(r, a) \
    asm volatile("ldmatrix.sync.aligned.m8n8.x4.shared.b16 {%0,%1,%2,%3}, [%4];" \
        : "=r"((r)[0]), "=r"((r)[1]), "=r"((r)[2]), "=r"((r)[3]) : "r"(a))

#define MMA_BF16(d, a, b0v, b1v) \
    asm volatile("mma.sync.aligned.m16n8k16.row.col.f32.bf16.bf16.f32 " \
        "{%0,%1,%2,%3}, {%4,%5,%6,%7}, {%8,%9}, {%0,%1,%2,%3};" \
        : "+f"((d)[0]), "+f"((d)[1]), "+f"((d)[2]), "+f"((d)[3]) \
        : "r"((a)[0]), "r"((a)[1]), "r"((a)[2]), "r"((a)[3]), "r"(b0v), "r"(b1v))

// ---------------- stage 128 rows x 64 bf16 (128B/row), XOR-swizzled ----------------
__device__ __forceinline__ void stage_tile(const __nv_bfloat16* g, int ld,
                                           uint32_t sbase, int tid) {
#pragma unroll
    for (int it = 0; it < 4; ++it) {
        int idx = tid + it * 256;           // 1024 16B chunks
        int row = idx >> 3, c = idx & 7;
        uint32_t saddr = sbase + row * 128 + ((c ^ (row & 7)) << 4);
        CP_ASYNC16(saddr, (const char*)(g + (size_t)row * ld) + c * 16);
    }
}

// ---------------- bf16 HMMA GEMM: out[M,N] = A[M,K] * B[N,K]^T (exact int) ----------------
// block 128x128, BK=64, 8 warps (2x4), warp tile 64x32, 3-stage cp.async pipeline
#define STAGE_BYTES 32768
template <int MODE>  // 1: xq@w1 +bias+gelu -> g_h ; 2: hq@w2 +bias -> out
__global__ void __launch_bounds__(256, 2) gemm_hmma(const float* __restrict__ bias,
                                                    float* __restrict__ outp, int yoff) {
    extern __shared__ __align__(128) char smem[];

    constexpr int K = (MODE == 1) ? D_MODEL : D_FF;
    constexpr int KITERS = K / 64;
    constexpr int LDOUT = (MODE == 1) ? D_FF : D_MODEL;
    const __nv_bfloat16* A = (MODE == 1) ? g_xq : g_hq;
    const __nv_bfloat16* B = (MODE == 1) ? g_w1q : g_w2q;
    const float* rowinv = (MODE == 1) ? g_xinv : g_hinv;
    float* out = (MODE == 1) ? g_h : outp;

    const int tid = threadIdx.x;
    const int wid = tid >> 5, lane = tid & 31;
    const int warpM = wid >> 2, warpN = wid & 3;
    const int m0 = (blockIdx.y + yoff) * 128, n0 = blockIdx.x * 128;

    const __nv_bfloat16* Abase = A + (size_t)m0 * K;
    const __nv_bfloat16* Bbase = B + (size_t)n0 * K;

    uint32_t sbase = s2u(smem);
    const int lr = lane & 7, gq = lane >> 3;

    // per-lane ldmatrix bases (row&7 == lr for all fragment rows)
    const uint32_t aRow = (uint32_t)(warpM * 64 + lr + ((gq & 1) << 3));
    const uint32_t bRow = (uint32_t)(warpN * 32 + lr + ((gq >> 1) << 3));
    const int aCsel = gq >> 1;   // chunk adder for A
    const int bCsel = gq & 1;    // chunk adder for B

    float acc[4][4][4];
#pragma unroll
    for (int i = 0; i < 4; i++)
#pragma unroll
        for (int j = 0; j < 4; j++)
#pragma unroll
            for (int r = 0; r < 4; r++) acc[i][j][r] = 0.f;

    // prologue: stages 0 and 1
    stage_tile(Abase, K, sbase + 0 * STAGE_BYTES, tid);
    stage_tile(Bbase, K, sbase + 0 * STAGE_BYTES + 16384, tid);
    CP_COMMIT();
    stage_tile(Abase + 64, K, sbase + 1 * STAGE_BYTES, tid);
    stage_tile(Bbase + 64, K, sbase + 1 * STAGE_BYTES + 16384, tid);
    CP_COMMIT();

    for (int kt = 0; kt < KITERS; ++kt) {
        CP_WAIT(1);
        __syncthreads();
        if (kt + 2 < KITERS) {
            const uint32_t sn = sbase + ((kt + 2) % 3) * STAGE_BYTES;
            stage_tile(Abase + (kt + 2) * 64, K, sn, tid);
            stage_tile(Bbase + (kt + 2) * 64, K, sn + 16384, tid);
        }
        CP_COMMIT();  // always exactly one group per iter

        const uint32_t sA = sbase + (kt % 3) * STAGE_BYTES;
        const uint32_t sB = sA + 16384;
        const uint32_t aLane = sA + aRow * 128;
        const uint32_t bLane = sB + bRow * 128;
#pragma unroll
        for (int ks = 0; ks < 4; ++ks) {
            uint32_t ar[4][4], br[2][4];
            const uint32_t ca = (uint32_t)(((ks * 2 + aCsel) ^ lr) << 4);
            const uint32_t cb = (uint32_t)(((ks * 2 + bCsel) ^ lr) << 4);
#pragma unroll
            for (int i = 0; i < 4; i++) LDSM_X4(ar[i], aLane + i * 2048 + ca);
#pragma unroll
            for (int jp = 0; jp < 2; jp++) LDSM_X4(br[jp], bLane + jp * 2048 + cb);
#pragma unroll
            for (int i = 0; i < 4; i++)
#pragma unroll
                for (int j = 0; j < 4; j++)
                    MMA_BF16(acc[i][j], ar[i], br[j >> 1][(j & 1) * 2],
                             br[j >> 1][(j & 1) * 2 + 1]);
        }
        __syncthreads();
    }

    // ---------------- epilogue: scale + bias (+gelu), float2 stores ----------------
    const float ws = g_wscale[MODE - 1];
    const int rbase = m0 + warpM * 64 + (lane >> 2);
    const int cbase = n0 + warpN * 32 + (lane & 3) * 2;
#pragma unroll
    for (int i = 0; i < 4; i++) {
        const int r0 = rbase + i * 16;
        const float sc0 = rowinv[r0] * ws;
        const float sc1 = rowinv[r0 + 8] * ws;
#pragma unroll
        for (int j = 0; j < 4; j++) {
            const int c = cbase + j * 8;
            const float bx = bias[c], by = bias[c + 1];
            float2 v0, v1;
            v0.x = acc[i][j][0] * sc0 + bx;
            v0.y = acc[i][j][1] * sc0 + by;
            v1.x = acc[i][j][2] * sc1 + bx;
            v1.y = acc[i][j][3] * sc1 + by;
            if (MODE == 1) {
                v0.x = 0.5f * v0.x * (1.0f + erff(v0.x * 0.7071067811865476f));
                v0.y = 0.5f * v0.y * (1.0f + erff(v0.y * 0.7071067811865476f));
                v1.x = 0.5f * v1.x * (1.0f + erff(v1.x * 0.7071067811865476f));
                v1.y = 0.5f * v1.y * (1.0f + erff(v1.y * 0.7071067811865476f));
            }
            *(float2*)(out + (size_t)r0 * LDOUT + c) = v0;
            *(float2*)(out + (size_t)(r0 + 8) * LDOUT + c) = v1;
        }
    }
}

// ---------------- weight absmean (deterministic two-stage) ----------------
__global__ void absmean_stage1(const float* __restrict__ w, size_t n, int idx) {
    __shared__ double sh[256];
    double s = 0.0;
    for (size_t i = (size_t)blockIdx.x * 256 + threadIdx.x; i < n; i += (size_t)256 * 1024)
        s += fabsf(w[i]);
    sh[threadIdx.x] = s; __syncthreads();
    for (int st = 128; st > 0; st >>= 1) {
        if (threadIdx.x < st) sh[threadIdx.x] += sh[threadIdx.x + st];
        __syncthreads();
    }
    if (threadIdx.x == 0) g_part[idx][blockIdx.x] = sh[0];
}

__global__ void absmean_stage2(size_t n, int idx) {
    __shared__ double sh[256];
    int tid = threadIdx.x;
    double s = g_part[idx][tid] + g_part[idx][tid + 256] +
               g_part[idx][tid + 512] + g_part[idx][tid + 768];
    sh[tid] = s; __syncthreads();
    for (int st = 128; st > 0; st >>= 1) {
        if (tid < st) sh[tid] += sh[tid + st];
        __syncthreads();
    }
    if (tid == 0) g_wscale[idx] = (float)fmax(sh[0] / (double)n, 1e-8);
}

// ---------------- ternary weight quant -> bf16 (exact) ----------------
__global__ void quant_w_kernel(const float* __restrict__ w, size_t n, int idx) {
    float s = g_wscale[idx];
    __nv_bfloat16* q = (idx == 0) ? g_w1q : g_w2q;
    for (size_t i = (size_t)blockIdx.x * blockDim.x + threadIdx.x; i < n;
         i += (size_t)gridDim.x * blockDim.x) {
        float v = rintf(w[i] / s);
        v = fmaxf(-1.0f, fminf(1.0f, v));
        q[i] = __float2bfloat16(v);
    }
}

// ---------------- fused LN + per-token absmax int8 fake-quant -> bf16 (x) ----------------
__global__ void ln_quant_x_kernel(const float* __restrict__ x) {
    __shared__ float sh[256];
    const int t = blockIdx.x, tid = threadIdx.x;
    const float4* rp = (const float4*)(x + (size_t)t * D_MODEL);
    float4 v0 = rp[tid], v1 = rp[tid + 256];

    float s = v0.x + v0.y + v0.z + v0.w + v1.x + v1.y + v1.z + v1.w;
    sh[tid] = s; __syncthreads();
    for (int st = 128; st > 0; st >>= 1) { if (tid < st) sh[tid] += sh[tid + st]; __syncthreads(); }
    float mu = sh[0] * (1.0f / D_MODEL); __syncthreads();

    v0.x -= mu; v0.y -= mu; v0.z -= mu; v0.w -= mu;
    v1.x -= mu; v1.y -= mu; v1.z -= mu; v1.w -= mu;
    float vs = v0.x*v0.x + v0.y*v0.y + v0.z*v0.z + v0.w*v0.w
             + v1.x*v1.x + v1.y*v1.y + v1.z*v1.z + v1.w*v1.w;
    sh[tid] = vs; __syncthreads();
    for (int st = 128; st > 0; st >>= 1) { if (tid < st) sh[tid] += sh[tid + st]; __syncthreads(); }
    float rstd = rsqrtf(sh[0] * (1.0f / D_MODEL) + 1e-5f); __syncthreads();

    v0.x *= rstd; v0.y *= rstd; v0.z *= rstd; v0.w *= rstd;
    v1.x *= rstd; v1.y *= rstd; v1.z *= rstd; v1.w *= rstd;
    float am = fmaxf(fmaxf(fmaxf(fabsf(v0.x), fabsf(v0.y)), fmaxf(fabsf(v0.z), fabsf(v0.w))),
                     fmaxf(fmaxf(fabsf(v1.x), fabsf(v1.y)), fmaxf(fabsf(v1.z), fabsf(v1.w))));
    sh[tid] = am; __syncthreads();
    for (int st = 128; st > 0; st >>= 1) { if (tid < st) sh[tid] = fmaxf(sh[tid], sh[tid + st]); __syncthreads(); }
    float amax = fmaxf(sh[0], 1e-5f); __syncthreads();
    float scale = 127.0f / amax;

#define QV(a) fminf(127.f, fmaxf(-128.f, rintf((a) * scale)))
    __nv_bfloat162* qp = (__nv_bfloat162*)(g_xq + (size_t)t * D_MODEL);
    qp[2 * tid + 0]         = __floats2bfloat162_rn(QV(v0.x), QV(v0.y));
    qp[2 * tid + 1]         = __floats2bfloat162_rn(QV(v0.z), QV(v0.w));
    qp[2 * (tid + 256) + 0] = __floats2bfloat162_rn(QV(v1.x), QV(v1.y));
    qp[2 * (tid + 256) + 1] = __floats2bfloat162_rn(QV(v1.z), QV(v1.w));
    if (tid == 0) g_xinv[t] = amax * (1.0f / 127.0f);
}

// ---------------- fused LN + quant (h: d=8192) -> bf16 ----------------
__global__ void ln_quant_h_kernel() {
    __shared__ float sh[256];
    const int t = blockIdx.x, tid = threadIdx.x;
    const float4* rp = (const float4*)(g_h + (size_t)t * D_FF);
    float4 v[8];
    float s = 0.f;
#pragma unroll
    for (int j = 0; j < 8; j++) { v[j] = rp[j * 256 + tid]; s += v[j].x + v[j].y + v[j].z + v[j].w; }
    sh[tid] = s; __syncthreads();
    for (int st = 128; st > 0; st >>= 1) { if (tid < st) sh[tid] += sh[tid + st]; __syncthreads(); }
    float mu = sh[0] * (1.0f / D_FF); __syncthreads();

    float vs = 0.f;
#pragma unroll
    for (int j = 0; j < 8; j++) {
        v[j].x -= mu; v[j].y -= mu; v[j].z -= mu; v[j].w -= mu;
        vs += v[j].x*v[j].x + v[j].y*v[j].y + v[j].z*v[j].z + v[j].w*v[j].w;
    }
    sh[tid] = vs; __syncthreads();
    for (int st = 128; st > 0; st >>= 1) { if (tid < st) sh[tid] += sh[tid + st]; __syncthreads(); }
    float rstd = rsqrtf(sh[0] * (1.0f / D_FF) + 1e-5f); __syncthreads();

    float am = 0.f;
#pragma unroll
    for (int j = 0; j < 8; j++) {
        v[j].x *= rstd; v[j].y *= rstd; v[j].z *= rstd; v[j].w *= rstd;
        am = fmaxf(am, fmaxf(fmaxf(fabsf(v[j].x), fabsf(v[j].y)), fmaxf(fabsf(v[j].z), fabsf(v[j].w))));
    }
    sh[tid] = am; __syncthreads();
    for (int st = 128; st > 0; st >>= 1) { if (tid < st) sh[tid] = fmaxf(sh[tid], sh[tid + st]); __syncthreads(); }
    float amax = fmaxf(sh[0], 1e-5f); __syncthreads();
    float scale = 127.0f / amax;

    __nv_bfloat162* qp = (__nv_bfloat162*)(g_hq + (size_t)t * D_FF);
#pragma unroll
    for (int j = 0; j < 8; j++) {
        qp[2 * (j * 256 + tid) + 0] = __floats2bfloat162_rn(QV(v[j].x), QV(v[j].y));
        qp[2 * (j * 256 + tid) + 1] = __floats2bfloat162_rn(QV(v[j].z), QV(v[j].w));
    }
    if (tid == 0) g_hinv[t] = amax * (1.0f / 127.0f);
}

// ---------------- launch ----------------
extern "C" void kernel_launch(void* const* d_in, const int* in_sizes, int n_in,
                              void* d_out, int out_size) {
    (void)in_sizes; (void)n_in; (void)out_size;
    const float* x  = (const float*)d_in[0];
    const float* w1 = (const float*)d_in[1];
    const float* b1 = (const float*)d_in[2];
    const float* w2 = (const float*)d_in[3];
    const float* b2 = (const float*)d_in[4];
    float* out = (float*)d_out;

    const size_t NW = (size_t)D_FF * D_MODEL;
    const int GEMM_SMEM = 3 * STAGE_BYTES;  // 96 KB

    cudaFuncSetAttribute(gemm_hmma<1>, cudaFuncAttributeMaxDynamicSharedMemorySize, GEMM_SMEM);
    cudaFuncSetAttribute(gemm_hmma<2>, cudaFuncAttributeMaxDynamicSharedMemorySize, GEMM_SMEM);

    // w1 chain + gemm1 early so the ncu -s window lands on a GEMM launch
    absmean_stage1<<<1024, 256>>>(w1, NW, 0);                       // 0
    absmean_stage2<<<1, 256>>>(NW, 0);                              // 1
    quant_w_kernel<<<4096, 256>>>(w1, NW, 0);                       // 2
    ln_quant_x_kernel<<<TOKENS, 256>>>(x);                          // 3
    gemm_hmma<1><<<dim3(D_FF / 128, 32), 256, GEMM_SMEM>>>(b1, nullptr, 0);   // 4
    gemm_hmma<1><<<dim3(D_FF / 128, 32), 256, GEMM_SMEM>>>(b1, nullptr, 32);  // 5
    absmean_stage1<<<1024, 256>>>(w2, NW, 1);                       // 6
    absmean_stage2<<<1, 256>>>(NW, 1);                              // 7
    quant_w_kernel<<<4096, 256>>>(w2, NW, 1);                       // 8
    ln_quant_h_kernel<<<TOKENS, 256>>>();                           // 9
    gemm_hmma<2><<<dim3(D_MODEL / 128, 64), 256, GEMM_SMEM>>>(b2, out, 0);    // 10
}